// round 1
// baseline (speedup 1.0000x reference)
#include <cuda_runtime.h>
#include <cstdint>

#define BATCH 512
#define TLEN  8192
#define DTC   1e-3f
#define LW    256              // steps per warp-chunk
#define LS    8                // steps per lane
#define NW    (TLEN / LW)      // 32 warp-chunks per batch

// scratch (no cudaMalloc allowed)
__device__ float g_comp[BATCH * NW * 6];    // chunk affine composites (M00,M01,M10,M11,v0,v1)
__device__ float g_xstart[BATCH * NW * 2];  // state at start of each chunk

// result = mine ∘ prev  (prev applied first):  M = Mm*Mp ; v = Mm*vp + vm
__device__ __forceinline__ void compose(float& M00, float& M01, float& M10, float& M11,
                                        float& v0, float& v1,
                                        float pM00, float pM01, float pM10, float pM11,
                                        float pv0, float pv1) {
    float n00 = M00 * pM00 + M01 * pM10;
    float n01 = M00 * pM01 + M01 * pM11;
    float n10 = M10 * pM00 + M11 * pM10;
    float n11 = M10 * pM01 + M11 * pM11;
    float nv0 = M00 * pv0 + M01 * pv1 + v0;
    float nv1 = M10 * pv0 + M11 * pv1 + v1;
    M00 = n00; M01 = n01; M10 = n10; M11 = n11; v0 = nv0; v1 = nv1;
}

__device__ __forceinline__ void warp_inclusive_scan(float& M00, float& M01, float& M10, float& M11,
                                                    float& v0, float& v1, int lane) {
    #pragma unroll
    for (int d = 1; d < 32; d <<= 1) {
        float pM00 = __shfl_up_sync(0xffffffffu, M00, d);
        float pM01 = __shfl_up_sync(0xffffffffu, M01, d);
        float pM10 = __shfl_up_sync(0xffffffffu, M10, d);
        float pM11 = __shfl_up_sync(0xffffffffu, M11, d);
        float pv0  = __shfl_up_sync(0xffffffffu, v0,  d);
        float pv1  = __shfl_up_sync(0xffffffffu, v1,  d);
        if (lane >= d) compose(M00, M01, M10, M11, v0, v1, pM00, pM01, pM10, pM11, pv0, pv1);
    }
}

// Build per-step transform from xic (float4, row-major 2x2) and dy (float2)
__device__ __forceinline__ void step_transform(float4 q, float2 d,
                                               float a00, float a01, float a10, float a11,
                                               float c00, float c01, float c10, float c11,
                                               float& T00, float& T01, float& T10, float& T11,
                                               float& b0, float& b1) {
    T00 = 1.0f + DTC * (a00 - (q.x * c00 + q.y * c10));
    T01 =        DTC * (a01 - (q.x * c01 + q.y * c11));
    T10 =        DTC * (a10 - (q.z * c00 + q.w * c10));
    T11 = 1.0f + DTC * (a11 - (q.z * c01 + q.w * c11));
    b0  = q.x * d.x + q.y * d.y;
    b1  = q.z * d.x + q.w * d.y;
}

// ---------------- Kernel A: per-chunk affine composites ----------------
__global__ __launch_bounds__(256)
void kA(const float4* __restrict__ xic, const float2* __restrict__ dyv,
        const float* __restrict__ Ac, const float* __restrict__ Cm) {
    int gw   = (blockIdx.x * blockDim.x + threadIdx.x) >> 5;
    int lane = threadIdx.x & 31;
    int b = gw / NW, w = gw % NW;
    if (b >= BATCH) return;

    float c00 = __ldg(Cm + 0), c01 = __ldg(Cm + 1), c10 = __ldg(Cm + 2), c11 = __ldg(Cm + 3);
    float a00 = __ldg(Ac + 0), a01 = __ldg(Ac + 1), a10 = __ldg(Ac + 2), a11 = __ldg(Ac + 3);

    int t0 = w * LW + lane * LS;
    const float4* xp = xic + (size_t)b * TLEN + t0;
    const float2* dp = dyv + (size_t)b * TLEN + t0;

    float M00 = 1.f, M01 = 0.f, M10 = 0.f, M11 = 1.f, v0 = 0.f, v1 = 0.f;
    #pragma unroll
    for (int k = 0; k < LS; k++) {
        float4 q = __ldg(xp + k);
        float2 d = __ldg(dp + k);
        float T00, T01, T10, T11, b0, b1;
        step_transform(q, d, a00, a01, a10, a11, c00, c01, c10, c11, T00, T01, T10, T11, b0, b1);
        // running = step ∘ running
        float n00 = T00 * M00 + T01 * M10;
        float n01 = T00 * M01 + T01 * M11;
        float n10 = T10 * M00 + T11 * M10;
        float n11 = T10 * M01 + T11 * M11;
        float nv0 = T00 * v0 + T01 * v1 + b0;
        float nv1 = T10 * v0 + T11 * v1 + b1;
        M00 = n00; M01 = n01; M10 = n10; M11 = n11; v0 = nv0; v1 = nv1;
    }

    warp_inclusive_scan(M00, M01, M10, M11, v0, v1, lane);

    if (lane == 31) {
        float* o = g_comp + (size_t)(b * NW + w) * 6;
        o[0] = M00; o[1] = M01; o[2] = M10; o[3] = M11; o[4] = v0; o[5] = v1;
    }
}

// ---------------- Kernel B: per-batch scan of chunk composites ----------------
__global__ __launch_bounds__(256)
void kB() {
    int b    = blockIdx.x * (blockDim.x >> 5) + (threadIdx.x >> 5);
    int lane = threadIdx.x & 31;   // lane == chunk index w (NW == 32)
    if (b >= BATCH) return;

    const float* c = g_comp + (size_t)(b * NW + lane) * 6;
    float M00 = c[0], M01 = c[1], M10 = c[2], M11 = c[3], v0 = c[4], v1 = c[5];

    warp_inclusive_scan(M00, M01, M10, M11, v0, v1, lane);

    // x at END of chunk `lane` starting from x0=[1,0]:  M*[1,0] + v
    float xe0 = M00 + v0;
    float xe1 = M10 + v1;
    float xs0 = __shfl_up_sync(0xffffffffu, xe0, 1);
    float xs1 = __shfl_up_sync(0xffffffffu, xe1, 1);
    if (lane == 0) { xs0 = 1.f; xs1 = 0.f; }

    float* o = g_xstart + (size_t)(b * NW + lane) * 2;
    o[0] = xs0; o[1] = xs1;
}

// ---------------- Kernel C: apply + emit outputs ----------------
__global__ __launch_bounds__(256)
void kC(const float4* __restrict__ xic, const float2* __restrict__ dyv,
        const float* __restrict__ Ac, const float* __restrict__ Cm,
        float2* __restrict__ out) {
    int gw   = (blockIdx.x * blockDim.x + threadIdx.x) >> 5;
    int lane = threadIdx.x & 31;
    int b = gw / NW, w = gw % NW;
    if (b >= BATCH) return;

    float c00 = __ldg(Cm + 0), c01 = __ldg(Cm + 1), c10 = __ldg(Cm + 2), c11 = __ldg(Cm + 3);
    float a00 = __ldg(Ac + 0), a01 = __ldg(Ac + 1), a10 = __ldg(Ac + 2), a11 = __ldg(Ac + 3);

    int t0 = w * LW + lane * LS;
    const float4* xp = xic + (size_t)b * TLEN + t0;
    const float2* dp = dyv + (size_t)b * TLEN + t0;

    // load lane's 8 steps into registers; build lane composite
    float4 q[LS];
    float2 d[LS];
    float M00 = 1.f, M01 = 0.f, M10 = 0.f, M11 = 1.f, v0 = 0.f, v1 = 0.f;
    #pragma unroll
    for (int k = 0; k < LS; k++) {
        q[k] = __ldg(xp + k);
        d[k] = __ldg(dp + k);
        float T00, T01, T10, T11, b0, b1;
        step_transform(q[k], d[k], a00, a01, a10, a11, c00, c01, c10, c11, T00, T01, T10, T11, b0, b1);
        float n00 = T00 * M00 + T01 * M10;
        float n01 = T00 * M01 + T01 * M11;
        float n10 = T10 * M00 + T11 * M10;
        float n11 = T10 * M01 + T11 * M11;
        float nv0 = T00 * v0 + T01 * v1 + b0;
        float nv1 = T10 * v0 + T11 * v1 + b1;
        M00 = n00; M01 = n01; M10 = n10; M11 = n11; v0 = nv0; v1 = nv1;
    }

    // exclusive scan: prefix of lanes < lane
    warp_inclusive_scan(M00, M01, M10, M11, v0, v1, lane);
    float pM00 = __shfl_up_sync(0xffffffffu, M00, 1);
    float pM01 = __shfl_up_sync(0xffffffffu, M01, 1);
    float pM10 = __shfl_up_sync(0xffffffffu, M10, 1);
    float pM11 = __shfl_up_sync(0xffffffffu, M11, 1);
    float pv0  = __shfl_up_sync(0xffffffffu, v0,  1);
    float pv1  = __shfl_up_sync(0xffffffffu, v1,  1);
    if (lane == 0) { pM00 = 1.f; pM01 = 0.f; pM10 = 0.f; pM11 = 1.f; pv0 = 0.f; pv1 = 0.f; }

    // state entering this lane's sub-chunk
    const float* xs = g_xstart + (size_t)(b * NW + w) * 2;
    float xw0 = xs[0], xw1 = xs[1];
    float x0 = pM00 * xw0 + pM01 * xw1 + pv0;
    float x1 = pM10 * xw0 + pM11 * xw1 + pv1;

    // replay from registers, emit out_t = DT * C @ x_t
    float2* op = out + (size_t)b * TLEN + t0;
    #pragma unroll
    for (int k = 0; k < LS; k++) {
        float2 o;
        o.x = DTC * (c00 * x0 + c01 * x1);
        o.y = DTC * (c10 * x0 + c11 * x1);
        op[k] = o;
        float T00, T01, T10, T11, b0, b1;
        step_transform(q[k], d[k], a00, a01, a10, a11, c00, c01, c10, c11, T00, T01, T10, T11, b0, b1);
        float nx0 = T00 * x0 + T01 * x1 + b0;
        float nx1 = T10 * x0 + T11 * x1 + b1;
        x0 = nx0; x1 = nx1;
    }
}

extern "C" void kernel_launch(void* const* d_in, const int* in_sizes, int n_in,
                              void* d_out, int out_size) {
    const float4* xic = (const float4*)d_in[0];   // [B,T,2,2] f32
    const float2* dyv = (const float2*)d_in[1];   // [B,T,2]   f32
    const float*  Ac  = (const float*)d_in[2];    // [2,2]
    const float*  Cm  = (const float*)d_in[3];    // [2,2]
    float2* out = (float2*)d_out;                 // [B,T,2]

    const int warpsAC   = BATCH * NW;             // 16384 warps
    const int blocksAC  = warpsAC * 32 / 256;     // 2048 blocks
    const int blocksB   = BATCH * 32 / 256;       // 64 blocks

    kA<<<blocksAC, 256>>>(xic, dyv, Ac, Cm);
    kB<<<blocksB, 256>>>();
    kC<<<blocksAC, 256>>>(xic, dyv, Ac, Cm, out);
}

// round 2
// speedup vs baseline: 1.4942x; 1.4942x over previous
#include <cuda_runtime.h>
#include <cstdint>

#define BATCH 512
#define TLEN  8192
#define DTC   1e-3f
#define LW    256              // steps per warp-chunk
#define LS    8                // steps per lane
#define NW    (TLEN / LW)      // 32 warp-chunks per batch
#define WPB   4                // warps per block (kA/kC)

// scratch (no cudaMalloc allowed)
__device__ float g_comp[BATCH * NW * 6];    // chunk affine composites
__device__ float g_xstart[BATCH * NW * 2];  // state at start of each chunk

// padded smem index: row = 8 steps + 1 pad slot -> conflict-free for
// coalesced writes (s = j*32+lane) AND lane-major reads (s = lane*8+k)
__device__ __forceinline__ int sidx(int s) { return (s >> 3) * 9 + (s & 7); }

__device__ __forceinline__ void compose(float& M00, float& M01, float& M10, float& M11,
                                        float& v0, float& v1,
                                        float pM00, float pM01, float pM10, float pM11,
                                        float pv0, float pv1) {
    float n00 = M00 * pM00 + M01 * pM10;
    float n01 = M00 * pM01 + M01 * pM11;
    float n10 = M10 * pM00 + M11 * pM10;
    float n11 = M10 * pM01 + M11 * pM11;
    float nv0 = M00 * pv0 + M01 * pv1 + v0;
    float nv1 = M10 * pv0 + M11 * pv1 + v1;
    M00 = n00; M01 = n01; M10 = n10; M11 = n11; v0 = nv0; v1 = nv1;
}

__device__ __forceinline__ void warp_inclusive_scan(float& M00, float& M01, float& M10, float& M11,
                                                    float& v0, float& v1, int lane) {
    #pragma unroll
    for (int d = 1; d < 32; d <<= 1) {
        float pM00 = __shfl_up_sync(0xffffffffu, M00, d);
        float pM01 = __shfl_up_sync(0xffffffffu, M01, d);
        float pM10 = __shfl_up_sync(0xffffffffu, M10, d);
        float pM11 = __shfl_up_sync(0xffffffffu, M11, d);
        float pv0  = __shfl_up_sync(0xffffffffu, v0,  d);
        float pv1  = __shfl_up_sync(0xffffffffu, v1,  d);
        if (lane >= d) compose(M00, M01, M10, M11, v0, v1, pM00, pM01, pM10, pM11, pv0, pv1);
    }
}

__device__ __forceinline__ void step_transform(float4 q, float2 d,
                                               float a00, float a01, float a10, float a11,
                                               float c00, float c01, float c10, float c11,
                                               float& T00, float& T01, float& T10, float& T11,
                                               float& b0, float& b1) {
    T00 = 1.0f + DTC * (a00 - (q.x * c00 + q.y * c10));
    T01 =        DTC * (a01 - (q.x * c01 + q.y * c11));
    T10 =        DTC * (a10 - (q.z * c00 + q.w * c10));
    T11 = 1.0f + DTC * (a11 - (q.z * c01 + q.w * c11));
    b0  = q.x * d.x + q.y * d.y;
    b1  = q.z * d.x + q.w * d.y;
}

// ---------------- Kernel A: per-chunk affine composites ----------------
__global__ __launch_bounds__(WPB * 32)
void kA(const float4* __restrict__ xic, const float2* __restrict__ dyv,
        const float* __restrict__ Ac, const float* __restrict__ Cm) {
    __shared__ float4 sq[WPB][32 * 9];
    __shared__ float2 sd[WPB][32 * 9];

    int wib  = threadIdx.x >> 5;
    int lane = threadIdx.x & 31;
    int gw = blockIdx.x * WPB + wib;
    int b = gw >> 5, w = gw & (NW - 1);

    float c00 = __ldg(Cm + 0), c01 = __ldg(Cm + 1), c10 = __ldg(Cm + 2), c11 = __ldg(Cm + 3);
    float a00 = __ldg(Ac + 0), a01 = __ldg(Ac + 1), a10 = __ldg(Ac + 2), a11 = __ldg(Ac + 3);

    size_t base = (size_t)b * TLEN + w * LW;
    const float4* xp = xic + base;
    const float2* dp = dyv + base;

    // coalesced stage: lane loads steps j*32+lane
    #pragma unroll
    for (int j = 0; j < 8; j++) {
        int s = j * 32 + lane;
        sq[wib][sidx(s)] = __ldg(xp + s);
        sd[wib][sidx(s)] = __ldg(dp + s);
    }
    __syncwarp();

    // compose this lane's 8 consecutive steps from smem
    float M00 = 1.f, M01 = 0.f, M10 = 0.f, M11 = 1.f, v0 = 0.f, v1 = 0.f;
    #pragma unroll
    for (int k = 0; k < LS; k++) {
        int s = lane * LS + k;
        float4 q = sq[wib][sidx(s)];
        float2 d = sd[wib][sidx(s)];
        float T00, T01, T10, T11, b0, b1;
        step_transform(q, d, a00, a01, a10, a11, c00, c01, c10, c11, T00, T01, T10, T11, b0, b1);
        float n00 = T00 * M00 + T01 * M10;
        float n01 = T00 * M01 + T01 * M11;
        float n10 = T10 * M00 + T11 * M10;
        float n11 = T10 * M01 + T11 * M11;
        float nv0 = T00 * v0 + T01 * v1 + b0;
        float nv1 = T10 * v0 + T11 * v1 + b1;
        M00 = n00; M01 = n01; M10 = n10; M11 = n11; v0 = nv0; v1 = nv1;
    }

    warp_inclusive_scan(M00, M01, M10, M11, v0, v1, lane);

    if (lane == 31) {
        float* o = g_comp + (size_t)(b * NW + w) * 6;
        o[0] = M00; o[1] = M01; o[2] = M10; o[3] = M11; o[4] = v0; o[5] = v1;
    }
}

// ---------------- Kernel B: per-batch scan of chunk composites ----------------
__global__ __launch_bounds__(256)
void kB() {
    int b    = blockIdx.x * (blockDim.x >> 5) + (threadIdx.x >> 5);
    int lane = threadIdx.x & 31;   // lane == chunk index w (NW == 32)
    if (b >= BATCH) return;

    const float* c = g_comp + (size_t)(b * NW + lane) * 6;
    float M00 = c[0], M01 = c[1], M10 = c[2], M11 = c[3], v0 = c[4], v1 = c[5];

    warp_inclusive_scan(M00, M01, M10, M11, v0, v1, lane);

    float xe0 = M00 + v0;            // x at END of chunk `lane` from x0=[1,0]
    float xe1 = M10 + v1;
    float xs0 = __shfl_up_sync(0xffffffffu, xe0, 1);
    float xs1 = __shfl_up_sync(0xffffffffu, xe1, 1);
    if (lane == 0) { xs0 = 1.f; xs1 = 0.f; }

    float* o = g_xstart + (size_t)(b * NW + lane) * 2;
    o[0] = xs0; o[1] = xs1;
}

// ---------------- Kernel C: apply + emit outputs ----------------
__global__ __launch_bounds__(WPB * 32)
void kC(const float4* __restrict__ xic, const float2* __restrict__ dyv,
        const float* __restrict__ Ac, const float* __restrict__ Cm,
        float2* __restrict__ out) {
    __shared__ float4 sq[WPB][32 * 9];
    __shared__ float2 sd[WPB][32 * 9];

    int wib  = threadIdx.x >> 5;
    int lane = threadIdx.x & 31;
    int gw = blockIdx.x * WPB + wib;
    int b = gw >> 5, w = gw & (NW - 1);

    float c00 = __ldg(Cm + 0), c01 = __ldg(Cm + 1), c10 = __ldg(Cm + 2), c11 = __ldg(Cm + 3);
    float a00 = __ldg(Ac + 0), a01 = __ldg(Ac + 1), a10 = __ldg(Ac + 2), a11 = __ldg(Ac + 3);

    size_t base = (size_t)b * TLEN + w * LW;
    const float4* xp = xic + base;
    const float2* dp = dyv + base;

    #pragma unroll
    for (int j = 0; j < 8; j++) {
        int s = j * 32 + lane;
        sq[wib][sidx(s)] = __ldg(xp + s);
        sd[wib][sidx(s)] = __ldg(dp + s);
    }
    __syncwarp();

    // lane composite from smem
    float M00 = 1.f, M01 = 0.f, M10 = 0.f, M11 = 1.f, v0 = 0.f, v1 = 0.f;
    #pragma unroll
    for (int k = 0; k < LS; k++) {
        int s = lane * LS + k;
        float4 q = sq[wib][sidx(s)];
        float2 d = sd[wib][sidx(s)];
        float T00, T01, T10, T11, b0, b1;
        step_transform(q, d, a00, a01, a10, a11, c00, c01, c10, c11, T00, T01, T10, T11, b0, b1);
        float n00 = T00 * M00 + T01 * M10;
        float n01 = T00 * M01 + T01 * M11;
        float n10 = T10 * M00 + T11 * M10;
        float n11 = T10 * M01 + T11 * M11;
        float nv0 = T00 * v0 + T01 * v1 + b0;
        float nv1 = T10 * v0 + T11 * v1 + b1;
        M00 = n00; M01 = n01; M10 = n10; M11 = n11; v0 = nv0; v1 = nv1;
    }

    // exclusive lane prefix
    warp_inclusive_scan(M00, M01, M10, M11, v0, v1, lane);
    float pM00 = __shfl_up_sync(0xffffffffu, M00, 1);
    float pM01 = __shfl_up_sync(0xffffffffu, M01, 1);
    float pM10 = __shfl_up_sync(0xffffffffu, M10, 1);
    float pM11 = __shfl_up_sync(0xffffffffu, M11, 1);
    float pv0  = __shfl_up_sync(0xffffffffu, v0,  1);
    float pv1  = __shfl_up_sync(0xffffffffu, v1,  1);
    if (lane == 0) { pM00 = 1.f; pM01 = 0.f; pM10 = 0.f; pM11 = 1.f; pv0 = 0.f; pv1 = 0.f; }

    const float* xs = g_xstart + (size_t)(b * NW + w) * 2;
    float xw0 = xs[0], xw1 = xs[1];
    float x0 = pM00 * xw0 + pM01 * xw1 + pv0;
    float x1 = pM10 * xw0 + pM11 * xw1 + pv1;

    // replay from smem, write out_t into the consumed dy slot (same shape)
    #pragma unroll
    for (int k = 0; k < LS; k++) {
        int s = lane * LS + k;
        float4 q = sq[wib][sidx(s)];
        float2 d = sd[wib][sidx(s)];
        float2 o;
        o.x = DTC * (c00 * x0 + c01 * x1);
        o.y = DTC * (c10 * x0 + c11 * x1);
        sd[wib][sidx(s)] = o;                 // overwrite consumed dy with output
        float T00, T01, T10, T11, b0, b1;
        step_transform(q, d, a00, a01, a10, a11, c00, c01, c10, c11, T00, T01, T10, T11, b0, b1);
        float nx0 = T00 * x0 + T01 * x1 + b0;
        float nx1 = T10 * x0 + T11 * x1 + b1;
        x0 = nx0; x1 = nx1;
    }
    __syncwarp();

    // coalesced output store
    float2* op = out + base;
    #pragma unroll
    for (int j = 0; j < 8; j++) {
        int s = j * 32 + lane;
        op[s] = sd[wib][sidx(s)];
    }
}

extern "C" void kernel_launch(void* const* d_in, const int* in_sizes, int n_in,
                              void* d_out, int out_size) {
    const float4* xic = (const float4*)d_in[0];   // [B,T,2,2] f32
    const float2* dyv = (const float2*)d_in[1];   // [B,T,2]   f32
    const float*  Ac  = (const float*)d_in[2];    // [2,2]
    const float*  Cm  = (const float*)d_in[3];    // [2,2]
    float2* out = (float2*)d_out;                 // [B,T,2]

    const int warpsAC  = BATCH * NW;              // 16384 warps
    const int blocksAC = warpsAC / WPB;           // 4096 blocks of 128 threads
    const int blocksB  = BATCH * 32 / 256;        // 64 blocks

    kA<<<blocksAC, WPB * 32>>>(xic, dyv, Ac, Cm);
    kB<<<blocksB, 256>>>();
    kC<<<blocksAC, WPB * 32>>>(xic, dyv, Ac, Cm, out);
}

// round 3
// speedup vs baseline: 1.8089x; 1.2106x over previous
#include <cuda_runtime.h>
#include <cstdint>

#define BATCH 512
#define TLEN  8192
#define DTC   1e-3f
#define TILE  2048             // steps per tile
#define NTILE (TLEN / TILE)    // 4
#define NWARP 8                // warps per block
#define NTHR  (NWARP * 32)     // 256
#define LS    (TILE / NTHR)    // 8 steps per lane

// padded smem index: row = 8 steps + 1 pad slot
__device__ __forceinline__ int sidx(int s) { return (s >> 3) * 9 + (s & 7); }
#define SQ_ELEMS ((TILE / 8) * 9)   // 2304 float4
#define SD_ELEMS ((TILE / 8) * 9)   // 2304 float2
#define SMEM_BYTES (SQ_ELEMS * 16 + SD_ELEMS * 8)

__device__ __forceinline__ void compose(float& M00, float& M01, float& M10, float& M11,
                                        float& v0, float& v1,
                                        float pM00, float pM01, float pM10, float pM11,
                                        float pv0, float pv1) {
    float n00 = M00 * pM00 + M01 * pM10;
    float n01 = M00 * pM01 + M01 * pM11;
    float n10 = M10 * pM00 + M11 * pM10;
    float n11 = M10 * pM01 + M11 * pM11;
    float nv0 = M00 * pv0 + M01 * pv1 + v0;
    float nv1 = M10 * pv0 + M11 * pv1 + v1;
    M00 = n00; M01 = n01; M10 = n10; M11 = n11; v0 = nv0; v1 = nv1;
}

__device__ __forceinline__ void warp_inclusive_scan(float& M00, float& M01, float& M10, float& M11,
                                                    float& v0, float& v1, int lane) {
    #pragma unroll
    for (int d = 1; d < 32; d <<= 1) {
        float pM00 = __shfl_up_sync(0xffffffffu, M00, d);
        float pM01 = __shfl_up_sync(0xffffffffu, M01, d);
        float pM10 = __shfl_up_sync(0xffffffffu, M10, d);
        float pM11 = __shfl_up_sync(0xffffffffu, M11, d);
        float pv0  = __shfl_up_sync(0xffffffffu, v0,  d);
        float pv1  = __shfl_up_sync(0xffffffffu, v1,  d);
        if (lane >= d) compose(M00, M01, M10, M11, v0, v1, pM00, pM01, pM10, pM11, pv0, pv1);
    }
}

__device__ __forceinline__ void step_transform(float4 q, float2 d,
                                               float a00, float a01, float a10, float a11,
                                               float c00, float c01, float c10, float c11,
                                               float& T00, float& T01, float& T10, float& T11,
                                               float& b0, float& b1) {
    T00 = 1.0f + DTC * (a00 - (q.x * c00 + q.y * c10));
    T01 =        DTC * (a01 - (q.x * c01 + q.y * c11));
    T10 =        DTC * (a10 - (q.z * c00 + q.w * c10));
    T11 = 1.0f + DTC * (a11 - (q.z * c01 + q.w * c11));
    b0  = q.x * d.x + q.y * d.y;
    b1  = q.z * d.x + q.w * d.y;
}

// ---------------- Fused single-pass kernel: one block per batch row ----------------
__global__ __launch_bounds__(NTHR)
void kFused(const float4* __restrict__ xic, const float2* __restrict__ dyv,
            const float* __restrict__ Ac, const float* __restrict__ Cm,
            float2* __restrict__ out) {
    extern __shared__ char smem[];
    float4* sq = (float4*)smem;                        // padded xic tile
    float2* sd = (float2*)(smem + SQ_ELEMS * 16);      // padded dy tile (reused for output)

    __shared__ float wc[NWARP][6];   // warp composites
    __shared__ float xs[NWARP][2];   // state at start of each warp's segment
    __shared__ float carry[2];       // state carried across tiles

    const int tid  = threadIdx.x;
    const int lane = tid & 31;
    const int w    = tid >> 5;
    const int b    = blockIdx.x;

    const float c00 = __ldg(Cm + 0), c01 = __ldg(Cm + 1), c10 = __ldg(Cm + 2), c11 = __ldg(Cm + 3);
    const float a00 = __ldg(Ac + 0), a01 = __ldg(Ac + 1), a10 = __ldg(Ac + 2), a11 = __ldg(Ac + 3);

    if (tid == 0) { carry[0] = 1.0f; carry[1] = 0.0f; }

    const size_t rowbase = (size_t)b * TLEN;

    for (int tile = 0; tile < NTILE; tile++) {
        const size_t base = rowbase + tile * TILE;
        const float4* xp = xic + base;
        const float2* dp = dyv + base;

        // --- coalesced stage into smem ---
        #pragma unroll
        for (int j = 0; j < TILE / NTHR; j++) {
            int s = j * NTHR + tid;
            sq[sidx(s)] = __ldg(xp + s);
            sd[sidx(s)] = __ldg(dp + s);
        }
        __syncthreads();

        // --- per-lane composite of LS consecutive steps ---
        const int s0 = w * (32 * LS) + lane * LS;
        float M00 = 1.f, M01 = 0.f, M10 = 0.f, M11 = 1.f, v0 = 0.f, v1 = 0.f;
        #pragma unroll
        for (int k = 0; k < LS; k++) {
            float4 q = sq[sidx(s0 + k)];
            float2 d = sd[sidx(s0 + k)];
            float T00, T01, T10, T11, b0, b1;
            step_transform(q, d, a00, a01, a10, a11, c00, c01, c10, c11, T00, T01, T10, T11, b0, b1);
            float n00 = T00 * M00 + T01 * M10;
            float n01 = T00 * M01 + T01 * M11;
            float n10 = T10 * M00 + T11 * M10;
            float n11 = T10 * M01 + T11 * M11;
            float nv0 = T00 * v0 + T01 * v1 + b0;
            float nv1 = T10 * v0 + T11 * v1 + b1;
            M00 = n00; M01 = n01; M10 = n10; M11 = n11; v0 = nv0; v1 = nv1;
        }

        warp_inclusive_scan(M00, M01, M10, M11, v0, v1, lane);

        if (lane == 31) {
            wc[w][0] = M00; wc[w][1] = M01; wc[w][2] = M10;
            wc[w][3] = M11; wc[w][4] = v0;  wc[w][5] = v1;
        }
        __syncthreads();

        // --- serial chain of 8 warp composites through the carry (thread 0) ---
        if (tid == 0) {
            float x0 = carry[0], x1 = carry[1];
            #pragma unroll
            for (int i = 0; i < NWARP; i++) {
                xs[i][0] = x0; xs[i][1] = x1;
                float nx0 = wc[i][0] * x0 + wc[i][1] * x1 + wc[i][4];
                float nx1 = wc[i][2] * x0 + wc[i][3] * x1 + wc[i][5];
                x0 = nx0; x1 = nx1;
            }
            carry[0] = x0; carry[1] = x1;
        }
        __syncthreads();

        // --- exclusive lane prefix, then replay emitting outputs ---
        float pM00 = __shfl_up_sync(0xffffffffu, M00, 1);
        float pM01 = __shfl_up_sync(0xffffffffu, M01, 1);
        float pM10 = __shfl_up_sync(0xffffffffu, M10, 1);
        float pM11 = __shfl_up_sync(0xffffffffu, M11, 1);
        float pv0  = __shfl_up_sync(0xffffffffu, v0,  1);
        float pv1  = __shfl_up_sync(0xffffffffu, v1,  1);
        if (lane == 0) { pM00 = 1.f; pM01 = 0.f; pM10 = 0.f; pM11 = 1.f; pv0 = 0.f; pv1 = 0.f; }

        float xw0 = xs[w][0], xw1 = xs[w][1];
        float x0 = pM00 * xw0 + pM01 * xw1 + pv0;
        float x1 = pM10 * xw0 + pM11 * xw1 + pv1;

        #pragma unroll
        for (int k = 0; k < LS; k++) {
            int si = sidx(s0 + k);
            float4 q = sq[si];
            float2 d = sd[si];
            float2 o;
            o.x = DTC * (c00 * x0 + c01 * x1);
            o.y = DTC * (c10 * x0 + c11 * x1);
            sd[si] = o;                       // overwrite consumed dy with output
            float T00, T01, T10, T11, b0, b1;
            step_transform(q, d, a00, a01, a10, a11, c00, c01, c10, c11, T00, T01, T10, T11, b0, b1);
            float nx0 = T00 * x0 + T01 * x1 + b0;
            float nx1 = T10 * x0 + T11 * x1 + b1;
            x0 = nx0; x1 = nx1;
        }
        __syncthreads();

        // --- coalesced output store ---
        float2* op = out + base;
        #pragma unroll
        for (int j = 0; j < TILE / NTHR; j++) {
            int s = j * NTHR + tid;
            op[s] = sd[sidx(s)];
        }
        __syncthreads();   // protect smem before next tile overwrites
    }
}

extern "C" void kernel_launch(void* const* d_in, const int* in_sizes, int n_in,
                              void* d_out, int out_size) {
    const float4* xic = (const float4*)d_in[0];   // [B,T,2,2] f32
    const float2* dyv = (const float2*)d_in[1];   // [B,T,2]   f32
    const float*  Ac  = (const float*)d_in[2];    // [2,2]
    const float*  Cm  = (const float*)d_in[3];    // [2,2]
    float2* out = (float2*)d_out;                 // [B,T,2]

    static bool attr_set = false;
    if (!attr_set) {
        cudaFuncSetAttribute(kFused, cudaFuncAttributeMaxDynamicSharedMemorySize, SMEM_BYTES);
        attr_set = true;
    }

    kFused<<<BATCH, NTHR, SMEM_BYTES>>>(xic, dyv, Ac, Cm, out);
}

// round 4
// speedup vs baseline: 2.1024x; 1.1623x over previous
#include <cuda_runtime.h>
#include <cstdint>

#define BATCH 512
#define TLEN  8192
#define DTC   1e-3f
#define TILE  1024             // steps per tile
#define NTILE (TLEN / TILE)    // 8
#define NWARP 8                // warps per block
#define NTHR  (NWARP * 32)     // 256
#define LS    (TILE / NTHR)    // 4 steps per lane

// padded smem index: row = 8 steps + 1 pad slot
__device__ __forceinline__ int sidx(int s) { return (s >> 3) * 9 + (s & 7); }
#define ROWS      (TILE / 8)            // 128
#define SQ_ELEMS  (ROWS * 9)            // 1152 float4
#define SD_ELEMS  (ROWS * 9)            // 1152 float2
#define SQ_BYTES  (SQ_ELEMS * 16)
#define SD_BYTES  (SD_ELEMS * 8)
#define BUF_BYTES (SQ_BYTES + SD_BYTES) // 27648
#define SMEM_BYTES (2 * BUF_BYTES)      // 55296

__device__ __forceinline__ void cp16(uint32_t dst, const void* src) {
    asm volatile("cp.async.cg.shared.global [%0], [%1], 16;" :: "r"(dst), "l"(src));
}
__device__ __forceinline__ void cp8(uint32_t dst, const void* src) {
    asm volatile("cp.async.ca.shared.global [%0], [%1], 8;" :: "r"(dst), "l"(src));
}
__device__ __forceinline__ void cp_commit() {
    asm volatile("cp.async.commit_group;");
}
template <int N>
__device__ __forceinline__ void cp_wait() {
    asm volatile("cp.async.wait_group %0;" :: "n"(N));
}

__device__ __forceinline__ void compose(float& M00, float& M01, float& M10, float& M11,
                                        float& v0, float& v1,
                                        float pM00, float pM01, float pM10, float pM11,
                                        float pv0, float pv1) {
    float n00 = M00 * pM00 + M01 * pM10;
    float n01 = M00 * pM01 + M01 * pM11;
    float n10 = M10 * pM00 + M11 * pM10;
    float n11 = M10 * pM01 + M11 * pM11;
    float nv0 = M00 * pv0 + M01 * pv1 + v0;
    float nv1 = M10 * pv0 + M11 * pv1 + v1;
    M00 = n00; M01 = n01; M10 = n10; M11 = n11; v0 = nv0; v1 = nv1;
}

__device__ __forceinline__ void warp_inclusive_scan(float& M00, float& M01, float& M10, float& M11,
                                                    float& v0, float& v1, int lane) {
    #pragma unroll
    for (int d = 1; d < 32; d <<= 1) {
        float pM00 = __shfl_up_sync(0xffffffffu, M00, d);
        float pM01 = __shfl_up_sync(0xffffffffu, M01, d);
        float pM10 = __shfl_up_sync(0xffffffffu, M10, d);
        float pM11 = __shfl_up_sync(0xffffffffu, M11, d);
        float pv0  = __shfl_up_sync(0xffffffffu, v0,  d);
        float pv1  = __shfl_up_sync(0xffffffffu, v1,  d);
        if (lane >= d) compose(M00, M01, M10, M11, v0, v1, pM00, pM01, pM10, pM11, pv0, pv1);
    }
}

__device__ __forceinline__ void step_transform(float4 q, float2 d,
                                               float a00, float a01, float a10, float a11,
                                               float c00, float c01, float c10, float c11,
                                               float& T00, float& T01, float& T10, float& T11,
                                               float& b0, float& b1) {
    T00 = 1.0f + DTC * (a00 - (q.x * c00 + q.y * c10));
    T01 =        DTC * (a01 - (q.x * c01 + q.y * c11));
    T10 =        DTC * (a10 - (q.z * c00 + q.w * c10));
    T11 = 1.0f + DTC * (a11 - (q.z * c01 + q.w * c11));
    b0  = q.x * d.x + q.y * d.y;
    b1  = q.z * d.x + q.w * d.y;
}

// ---------------- Fused pipelined kernel: one block per batch row ----------------
__global__ __launch_bounds__(NTHR)
void kFused(const float4* __restrict__ xic, const float2* __restrict__ dyv,
            const float* __restrict__ Ac, const float* __restrict__ Cm,
            float2* __restrict__ out) {
    extern __shared__ char smem[];

    __shared__ float wc[NWARP][6];   // warp composites
    __shared__ float xs[NWARP][2];   // state at start of each warp's segment
    __shared__ float carry[2];       // state carried across tiles

    const int tid  = threadIdx.x;
    const int lane = tid & 31;
    const int w    = tid >> 5;
    const int b    = blockIdx.x;

    const float c00 = __ldg(Cm + 0), c01 = __ldg(Cm + 1), c10 = __ldg(Cm + 2), c11 = __ldg(Cm + 3);
    const float a00 = __ldg(Ac + 0), a01 = __ldg(Ac + 1), a10 = __ldg(Ac + 2), a11 = __ldg(Ac + 3);

    if (tid == 0) { carry[0] = 1.0f; carry[1] = 0.0f; }

    const size_t rowbase = (size_t)b * TLEN;
    const uint32_t smem_u32 = (uint32_t)__cvta_generic_to_shared(smem);

    // stage tile `t` into buffer `buf` via cp.async (per-thread slots s = j*NTHR+tid)
    auto stage = [&](int t, int buf) {
        const uint32_t sq_u = smem_u32 + buf * BUF_BYTES;
        const uint32_t sd_u = sq_u + SQ_BYTES;
        const float4* xp = xic + rowbase + t * TILE;
        const float2* dp = dyv + rowbase + t * TILE;
        #pragma unroll
        for (int j = 0; j < TILE / NTHR; j++) {
            int s = j * NTHR + tid;
            int si = sidx(s);
            cp16(sq_u + si * 16, xp + s);
            cp8(sd_u + si * 8, dp + s);
        }
        cp_commit();
    };

    stage(0, 0);

    for (int tile = 0; tile < NTILE; tile++) {
        const int buf = tile & 1;
        float4* sq = (float4*)(smem + buf * BUF_BYTES);
        float2* sd = (float2*)(smem + buf * BUF_BYTES + SQ_BYTES);

        if (tile + 1 < NTILE) {
            stage(tile + 1, buf ^ 1);
            cp_wait<1>();       // current tile's group done, prefetch in flight
        } else {
            cp_wait<0>();
        }
        __syncthreads();

        // --- per-lane composite of LS consecutive steps ---
        const int s0 = w * (32 * LS) + lane * LS;
        float M00 = 1.f, M01 = 0.f, M10 = 0.f, M11 = 1.f, v0 = 0.f, v1 = 0.f;
        #pragma unroll
        for (int k = 0; k < LS; k++) {
            float4 q = sq[sidx(s0 + k)];
            float2 d = sd[sidx(s0 + k)];
            float T00, T01, T10, T11, b0, b1;
            step_transform(q, d, a00, a01, a10, a11, c00, c01, c10, c11, T00, T01, T10, T11, b0, b1);
            float n00 = T00 * M00 + T01 * M10;
            float n01 = T00 * M01 + T01 * M11;
            float n10 = T10 * M00 + T11 * M10;
            float n11 = T10 * M01 + T11 * M11;
            float nv0 = T00 * v0 + T01 * v1 + b0;
            float nv1 = T10 * v0 + T11 * v1 + b1;
            M00 = n00; M01 = n01; M10 = n10; M11 = n11; v0 = nv0; v1 = nv1;
        }

        warp_inclusive_scan(M00, M01, M10, M11, v0, v1, lane);

        if (lane == 31) {
            wc[w][0] = M00; wc[w][1] = M01; wc[w][2] = M10;
            wc[w][3] = M11; wc[w][4] = v0;  wc[w][5] = v1;
        }
        __syncthreads();

        // --- serial chain of warp composites through the carry (thread 0) ---
        if (tid == 0) {
            float x0 = carry[0], x1 = carry[1];
            #pragma unroll
            for (int i = 0; i < NWARP; i++) {
                xs[i][0] = x0; xs[i][1] = x1;
                float nx0 = wc[i][0] * x0 + wc[i][1] * x1 + wc[i][4];
                float nx1 = wc[i][2] * x0 + wc[i][3] * x1 + wc[i][5];
                x0 = nx0; x1 = nx1;
            }
            carry[0] = x0; carry[1] = x1;
        }
        __syncthreads();

        // --- exclusive lane prefix, then replay emitting outputs ---
        float pM00 = __shfl_up_sync(0xffffffffu, M00, 1);
        float pM01 = __shfl_up_sync(0xffffffffu, M01, 1);
        float pM10 = __shfl_up_sync(0xffffffffu, M10, 1);
        float pM11 = __shfl_up_sync(0xffffffffu, M11, 1);
        float pv0  = __shfl_up_sync(0xffffffffu, v0,  1);
        float pv1  = __shfl_up_sync(0xffffffffu, v1,  1);
        if (lane == 0) { pM00 = 1.f; pM01 = 0.f; pM10 = 0.f; pM11 = 1.f; pv0 = 0.f; pv1 = 0.f; }

        float xw0 = xs[w][0], xw1 = xs[w][1];
        float x0 = pM00 * xw0 + pM01 * xw1 + pv0;
        float x1 = pM10 * xw0 + pM11 * xw1 + pv1;

        #pragma unroll
        for (int k = 0; k < LS; k++) {
            int si = sidx(s0 + k);
            float4 q = sq[si];
            float2 d = sd[si];
            float2 o;
            o.x = DTC * (c00 * x0 + c01 * x1);
            o.y = DTC * (c10 * x0 + c11 * x1);
            sd[si] = o;                       // overwrite consumed dy with output
            float T00, T01, T10, T11, b0, b1;
            step_transform(q, d, a00, a01, a10, a11, c00, c01, c10, c11, T00, T01, T10, T11, b0, b1);
            float nx0 = T00 * x0 + T01 * x1 + b0;
            float nx1 = T10 * x0 + T11 * x1 + b1;
            x0 = nx0; x1 = nx1;
        }
        __syncthreads();   // replay writes (lane-major) -> store reads (coalesced)

        // --- coalesced output store (per-thread slots s = j*NTHR+tid, same as staging) ---
        float2* op = out + rowbase + tile * TILE;
        #pragma unroll
        for (int j = 0; j < TILE / NTHR; j++) {
            int s = j * NTHR + tid;
            op[s] = sd[sidx(s)];
        }
        // no barrier needed: next overwrite of this buffer (cp.async at tile+1 and
        // replay writes at tile+2) touches per-thread slots we just read ourselves,
        // or is fenced by the barriers above.
    }
}

extern "C" void kernel_launch(void* const* d_in, const int* in_sizes, int n_in,
                              void* d_out, int out_size) {
    const float4* xic = (const float4*)d_in[0];   // [B,T,2,2] f32
    const float2* dyv = (const float2*)d_in[1];   // [B,T,2]   f32
    const float*  Ac  = (const float*)d_in[2];    // [2,2]
    const float*  Cm  = (const float*)d_in[3];    // [2,2]
    float2* out = (float2*)d_out;                 // [B,T,2]

    static bool attr_set = false;
    if (!attr_set) {
        cudaFuncSetAttribute(kFused, cudaFuncAttributeMaxDynamicSharedMemorySize, SMEM_BYTES);
        attr_set = true;
    }

    kFused<<<BATCH, NTHR, SMEM_BYTES>>>(xic, dyv, Ac, Cm, out);
}